// round 14
// baseline (speedup 1.0000x reference)
#include <cuda_runtime.h>
#include <cstdint>
#include <cstddef>

#define N_NODES 50000
#define E_EDGES 800000
#define DIM 256
#define H_HEADS 8
#define LAMBDA_INIT 0.63212055882855767840f

// ---------------- scratch (device globals; no allocation allowed) ----------------
__device__ __align__(16) float g_V[(size_t)N_NODES * DIM];     // x @ v_w.T
__device__ __align__(16) float g_acc[(size_t)N_NODES * DIM];   // segment_sum output
__device__ __align__(16) float g_exp[(size_t)E_EDGES * 16];    // exp(edge scores)
__device__ __align__(16) float g_sums[(size_t)N_NODES * 16];   // per-target softmax sums
__device__ int g_src[E_EDGES];
__device__ int g_tgt[E_EDGES];
__device__ int g_is64;
__device__ float g_beta;
__device__ __align__(16) float g_vtest[4];
__device__ int g_vec_ok;

__device__ __forceinline__ void red_add_f32x4_raw(float4* addr, float a, float b, float c, float d) {
    asm volatile("red.global.add.v4.f32 [%0], {%1,%2,%3,%4};"
                 :: "l"(addr), "f"(a), "f"(b), "f"(c), "f"(d) : "memory");
}

__device__ __forceinline__ void red_add4(int vec_ok, float* addr, float a, float b, float c, float d) {
    if (vec_ok) {
        red_add_f32x4_raw((float4*)addr, a, b, c, d);
    } else {
        atomicAdd(addr + 0, a);
        atomicAdd(addr + 1, b);
        atomicAdd(addr + 2, c);
        atomicAdd(addr + 3, d);
    }
}

// ---------------- red.v4 self-test ----------------
__global__ void vtest_init_kernel() { if (threadIdx.x < 4) g_vtest[threadIdx.x] = 0.f; }
__global__ void vtest_run_kernel()  { if (threadIdx.x == 0) red_add_f32x4_raw((float4*)g_vtest, 1.f, 2.f, 3.f, 4.f); }
__global__ void vtest_check_kernel() {
    if (threadIdx.x == 0)
        g_vec_ok = (g_vtest[0] == 1.f && g_vtest[1] == 2.f &&
                    g_vtest[2] == 3.f && g_vtest[3] == 4.f) ? 1 : 0;
}

// ---------------- edge_index dtype detection + canonicalization ----------------
__global__ void detect_kernel(const void* __restrict__ ei) {
    const long long* p = (const long long*)ei;
    int bad = 0;
    for (int i = threadIdx.x; i < 2048; i += 256) {
        long long v = p[i];
        if (v < 0 || v >= N_NODES) bad = 1;
    }
    bad = __syncthreads_or(bad);
    if (threadIdx.x == 0) g_is64 = !bad;
}

__global__ void convert_kernel(const void* __restrict__ ei) {
    int e = blockIdx.x * 256 + threadIdx.x;
    if (e >= E_EDGES) return;
    long long s, t;
    if (g_is64) {
        const long long* p = (const long long*)ei;
        s = p[e];
        t = p[(size_t)E_EDGES + e];
    } else {
        const int* p = (const int*)ei;
        s = p[e];
        t = p[E_EDGES + e];
    }
    if (s < 0) s = 0; if (s >= N_NODES) s = N_NODES - 1;
    if (t < 0) t = 0; if (t >= N_NODES) t = N_NODES - 1;
    g_src[e] = (int)s;
    g_tgt[e] = (int)t;
}

// ---------------- beta ----------------
__global__ void beta_kernel(const float* __restrict__ lq, const float* __restrict__ lk,
                            float* beta_slot) {
    __shared__ float red[4];
    int t = threadIdx.x;
    float v = (t < 100) ? lq[t] * lk[t] : 0.f;
    #pragma unroll
    for (int o = 16; o; o >>= 1) v += __shfl_down_sync(0xffffffffu, v, o);
    if ((t & 31) == 0) red[t >> 5] = v;
    __syncthreads();
    if (t == 0) {
        float s = red[0] + red[1] + red[2] + red[3];
        float lam = expf(s);
        float beta = 1.f / (1.f + expf(-lam * LAMBDA_INIT));
        g_beta = beta;
        if (beta_slot) *beta_slot = beta;
    }
}

// ---------------- zero ----------------
__global__ void zero_kernel() {
    const float4 z = make_float4(0.f, 0.f, 0.f, 0.f);
    size_t stride = (size_t)gridDim.x * blockDim.x;
    size_t i = (size_t)blockIdx.x * blockDim.x + threadIdx.x;
    float4* a = (float4*)g_acc;
    float4* s = (float4*)g_sums;
    for (size_t k = i; k < (size_t)N_NODES * DIM / 4; k += stride) a[k] = z;
    for (size_t k = i; k < (size_t)N_NODES * 16 / 4;  k += stride) s[k] = z;
}

// ---------------- GEMM NT: C[i,j] = dot(A[i,:], B[j,:]) ----------------
__global__ __launch_bounds__(256) void gemm_nt(const float* __restrict__ A,
                                               const float* __restrict__ B,
                                               float* __restrict__ C, int M) {
    __shared__ __align__(16) float As[16][132];
    __shared__ __align__(16) float Bs[16][64];
    const int tid = threadIdx.x;
    const int bm = blockIdx.x * 128;
    const int bn = blockIdx.y * 64;
    const int tx = tid & 15;
    const int ty = tid >> 4;
    const int lrow = tid >> 2;
    const int lkq  = tid & 3;

    float acc[8][4];
    #pragma unroll
    for (int i = 0; i < 8; i++)
        #pragma unroll
        for (int j = 0; j < 4; j++) acc[i][j] = 0.f;

    for (int kt = 0; kt < 256; kt += 16) {
        #pragma unroll
        for (int half = 0; half < 2; half++) {
            int r = lrow + half * 64;
            int gr = bm + r;
            float4 v = make_float4(0.f, 0.f, 0.f, 0.f);
            if (gr < M) v = *(const float4*)&A[(size_t)gr * 256 + kt + lkq * 4];
            As[lkq * 4 + 0][r] = v.x;
            As[lkq * 4 + 1][r] = v.y;
            As[lkq * 4 + 2][r] = v.z;
            As[lkq * 4 + 3][r] = v.w;
        }
        {
            float4 v = *(const float4*)&B[(size_t)(bn + lrow) * 256 + kt + lkq * 4];
            Bs[lkq * 4 + 0][lrow] = v.x;
            Bs[lkq * 4 + 1][lrow] = v.y;
            Bs[lkq * 4 + 2][lrow] = v.z;
            Bs[lkq * 4 + 3][lrow] = v.w;
        }
        __syncthreads();
        #pragma unroll
        for (int kk = 0; kk < 16; kk++) {
            float4 b  = *(const float4*)&Bs[kk][tx * 4];
            float4 a0 = *(const float4*)&As[kk][ty * 8];
            float4 a1 = *(const float4*)&As[kk][ty * 8 + 4];
            float av[8] = {a0.x, a0.y, a0.z, a0.w, a1.x, a1.y, a1.z, a1.w};
            float bv[4] = {b.x, b.y, b.z, b.w};
            #pragma unroll
            for (int i = 0; i < 8; i++)
                #pragma unroll
                for (int j = 0; j < 4; j++)
                    acc[i][j] = fmaf(av[i], bv[j], acc[i][j]);
        }
        __syncthreads();
    }
    #pragma unroll
    for (int i = 0; i < 8; i++) {
        int gr = bm + ty * 8 + i;
        if (gr < M) {
            float4 o = make_float4(acc[i][0], acc[i][1], acc[i][2], acc[i][3]);
            *(float4*)&C[(size_t)gr * 256 + bn + tx * 4] = o;
        }
    }
}

// ---------------- edge MLP ----------------
__global__ __launch_bounds__(256) void mlp_kernel(const float* __restrict__ edge_attr,
                                                  const float* __restrict__ w1,
                                                  const float* __restrict__ b1,
                                                  const float* __restrict__ w2,
                                                  const float* __restrict__ b2) {
    __shared__ __align__(16) float s_w1[256 * 8];
    __shared__ float s_b1[256];
    __shared__ __align__(16) float s_w2[16 * 256];
    __shared__ float s_b2[16];
    const int tid = threadIdx.x;
    for (int i = tid; i < 2048; i += 256) {
        int d = i >> 3, j = i & 7;
        s_w1[i] = (j < 6) ? w1[d * 6 + j] : 0.f;
    }
    s_b1[tid] = b1[tid];
    for (int i = tid; i < 4096; i += 256) s_w2[i] = w2[i];
    if (tid < 16) s_b2[tid] = b2[tid];
    __syncthreads();

    const int vec_ok = g_vec_ok;
    const int e = blockIdx.x * 256 + tid;
    float ea0 = edge_attr[(size_t)e * 6 + 0];
    float ea1 = edge_attr[(size_t)e * 6 + 1];
    float ea2 = edge_attr[(size_t)e * 6 + 2];
    float ea3 = edge_attr[(size_t)e * 6 + 3];
    float ea4 = edge_attr[(size_t)e * 6 + 4];
    float ea5 = edge_attr[(size_t)e * 6 + 5];

    float sc[16];
    #pragma unroll
    for (int j = 0; j < 16; j++) sc[j] = s_b2[j];

    for (int c = 0; c < 256; c += 16) {
        float hv[16];
        #pragma unroll
        for (int i = 0; i < 16; i++) {
            int d = c + i;
            float4 wA = *(const float4*)&s_w1[d * 8];
            float4 wB = *(const float4*)&s_w1[d * 8 + 4];
            float z = s_b1[d];
            z = fmaf(wA.x, ea0, z);
            z = fmaf(wA.y, ea1, z);
            z = fmaf(wA.z, ea2, z);
            z = fmaf(wA.w, ea3, z);
            z = fmaf(wB.x, ea4, z);
            z = fmaf(wB.y, ea5, z);
            hv[i] = 0.5f * z * (1.0f + erff(z * 0.70710678118654752f));
        }
        #pragma unroll
        for (int j = 0; j < 16; j++) {
            const float4* wr = (const float4*)&s_w2[j * 256 + c];
            float s = sc[j];
            #pragma unroll
            for (int i2 = 0; i2 < 4; i2++) {
                float4 w = wr[i2];
                s = fmaf(w.x, hv[4 * i2 + 0], s);
                s = fmaf(w.y, hv[4 * i2 + 1], s);
                s = fmaf(w.z, hv[4 * i2 + 2], s);
                s = fmaf(w.w, hv[4 * i2 + 3], s);
            }
            sc[j] = s;
        }
    }
    int tgt = g_tgt[e];
    float ex[16];
    #pragma unroll
    for (int j = 0; j < 16; j++) ex[j] = expf(sc[j]);
    float4* eo = (float4*)&g_exp[(size_t)e * 16];
    #pragma unroll
    for (int q = 0; q < 4; q++) {
        eo[q] = make_float4(ex[4 * q], ex[4 * q + 1], ex[4 * q + 2], ex[4 * q + 3]);
        red_add4(vec_ok, &g_sums[(size_t)tgt * 16 + 4 * q],
                 ex[4 * q], ex[4 * q + 1], ex[4 * q + 2], ex[4 * q + 3]);
    }
}

// ---------------- scatter ----------------
__global__ __launch_bounds__(256) void scatter_kernel(float* __restrict__ d_attn) {
    int gw = (int)(((size_t)blockIdx.x * 256 + threadIdx.x) >> 5);
    int lane = threadIdx.x & 31;
    if (gw >= E_EDGES) return;
    const int vec_ok = g_vec_ok;
    int src = g_src[gw];
    int tgt = g_tgt[gw];
    float beta = g_beta;
    float attn = 0.f;
    if (lane < 8) {
        float2 e12 = ((const float2*)g_exp)[(size_t)gw * 8 + lane];
        float2 s12 = ((const float2*)g_sums)[(size_t)tgt * 8 + lane];
        attn = e12.x / s12.x - beta * (e12.y / s12.y);
        if (d_attn) d_attn[(size_t)gw * 8 + lane] = attn;
    }
    const float4* vsrc = (const float4*)(g_V + (size_t)src * 256);
    float* adst = g_acc + (size_t)tgt * 256;
    #pragma unroll
    for (int h = 0; h < 2; h++) {
        int q = lane + h * 32;
        float w = __shfl_sync(0xffffffffu, attn, q >> 3);
        float4 v = vsrc[q];
        red_add4(vec_ok, adst + 4 * q, w * v.x, w * v.y, w * v.z, w * v.w);
    }
}

// ---------------- diagnostic tripwire (reads REAL device symbols) ----------------
// codes: 1e2 g_V==0 | 1e4 g_exp==0 | 1e6 g_sums==0 | 1e8 g_acc==0 | 1e10 out==0
// multipliers: x3 int32-index path, x7 red.v4 probe failed, x13 n_in != 11
__global__ void diag_kernel(float* __restrict__ out, int extra_mult) {
    int ok_V = 0, ok_e = 0, ok_s = 0, ok_a = 0, ok_o = 0;
    for (int i = threadIdx.x; i < 4096; i += 256) {
        if (fabsf(g_V[i])   > 1e-12f) ok_V = 1;
        if (g_exp[i]        > 1e-20f) ok_e = 1;
        if (g_sums[i]       > 1e-20f) ok_s = 1;
        if (fabsf(g_acc[i]) > 1e-12f) ok_a = 1;
        if (fabsf(out[i])   > 1e-9f)  ok_o = 1;
    }
    ok_V = __syncthreads_or(ok_V);
    ok_e = __syncthreads_or(ok_e);
    ok_s = __syncthreads_or(ok_s);
    ok_a = __syncthreads_or(ok_a);
    ok_o = __syncthreads_or(ok_o);
    float code = 0.f;
    if      (!ok_V) code = 1e2f;
    else if (!ok_e) code = 1e4f;
    else if (!ok_s) code = 1e6f;
    else if (!ok_a) code = 1e8f;
    else if (!ok_o) code = 1e10f;
    if (code != 0.f) {
        code *= (g_is64 ? 1.f : 3.f);
        code *= (g_vec_ok ? 1.f : 7.f);
        code *= (float)extra_mult;
        size_t stride = (size_t)gridDim.x * blockDim.x;
        for (size_t i = (size_t)blockIdx.x * blockDim.x + threadIdx.x;
             i < (size_t)N_NODES * DIM; i += stride)
            out[i] = code;
    }
}

// ---------------- launch ----------------
extern "C" void kernel_launch(void* const* d_in, const int* in_sizes, int n_in,
                              void* d_out, int out_size) {
    int i_x = -1, i_ea = -1, i_ei = -1, i_w1 = -1, i_b1 = -1, i_w2 = -1, i_b2 = -1;
    int sq65536[2] = {-1, -1};
    int sq100[2]   = {-1, -1};
    for (int i = 0; i < n_in; i++) {
        int s = in_sizes[i];
        switch (s) {
            case 12800000: i_x = i; break;
            case 4800000:  i_ea = i; break;
            case 1600000: case 3200000: i_ei = i; break;
            case 1536:     i_w1 = i; break;
            case 256:      i_b1 = i; break;
            case 4096:     i_w2 = i; break;
            case 16:       i_b2 = i; break;
            case 65536:    if (sq65536[0] < 0) sq65536[0] = i; else sq65536[1] = i; break;
            case 100:      if (sq100[0] < 0) sq100[0] = i; else sq100[1] = i; break;
            default: break;
        }
    }
    const size_t OUT_SZ  = (size_t)N_NODES * DIM;
    const size_t ATTN_SZ = (size_t)E_EDGES * H_HEADS;

    bool found = (i_x >= 0) && (i_ea >= 0) && (i_ei >= 0) && (i_w1 >= 0) && (i_b1 >= 0) &&
                 (i_w2 >= 0) && (i_b2 >= 0) && (sq65536[1] >= 0) && (sq100[1] >= 0);
    if (!found) {
        cudaMemsetAsync((void*)d_out, 0x7E, OUT_SZ * sizeof(float));   // ~8.46e37: size table wrong
        return;
    }

    // ---- THE FIX: resolve REAL device addresses of __device__ globals.
    // Host-side `g_V`/`g_acc` are host shadow symbols; on GB300 (ATS) passing
    // them silently made kernels read/write HOST memory.
    float *pV = nullptr, *pAcc = nullptr;
    cudaGetSymbolAddress((void**)&pV, g_V);
    cudaGetSymbolAddress((void**)&pAcc, g_acc);
    if (!pV || !pAcc) {
        cudaMemsetAsync((void*)d_out, 0x7D, OUT_SZ * sizeof(float));   // ~2.1e37: symbol lookup failed
        return;
    }

    int i_vw, i_ow;
    if (i_x == 0) { i_vw = sq65536[0]; i_ow = sq65536[1]; }
    else          { i_ow = sq65536[0]; i_vw = sq65536[1]; }

    const float* x         = (const float*)d_in[i_x];
    const float* edge_attr = (const float*)d_in[i_ea];
    const float* v_w       = (const float*)d_in[i_vw];
    const float* out_w     = (const float*)d_in[i_ow];
    const float* e_w1      = (const float*)d_in[i_w1];
    const float* e_b1      = (const float*)d_in[i_b1];
    const float* e_w2      = (const float*)d_in[i_w2];
    const float* e_b2      = (const float*)d_in[i_b2];
    const float* lq        = (const float*)d_in[sq100[0]];
    const float* lk        = (const float*)d_in[sq100[1]];
    const void*  ei        = (const void*)d_in[i_ei];

    float* out = (float*)d_out;
    float* d_attn = nullptr;
    float* d_beta = nullptr;
    if ((size_t)out_size >= OUT_SZ + ATTN_SZ)     d_attn = out + OUT_SZ;
    if ((size_t)out_size >= OUT_SZ + ATTN_SZ + 1) d_beta = out + OUT_SZ + ATTN_SZ;

    cudaGetLastError();   // clear stale errors

    vtest_init_kernel<<<1, 32>>>();
    vtest_run_kernel<<<1, 32>>>();
    vtest_check_kernel<<<1, 32>>>();

    detect_kernel<<<1, 256>>>(ei);
    convert_kernel<<<(E_EDGES + 255) / 256, 256>>>(ei);

    beta_kernel<<<1, 128>>>(lq, lk, d_beta);
    zero_kernel<<<1024, 256>>>();

    dim3 ggrid((N_NODES + 127) / 128, DIM / 64);
    gemm_nt<<<ggrid, 256>>>(x, v_w, pV, N_NODES);                  // V = x @ v_w.T  (REAL g_V)

    mlp_kernel<<<E_EDGES / 256, 256>>>(edge_attr, e_w1, e_b1, e_w2, e_b2);

    scatter_kernel<<<E_EDGES / 8, 256>>>(d_attn);                  // 1 warp per edge

    gemm_nt<<<ggrid, 256>>>(pAcc, out_w, out, N_NODES);            // out = acc @ out_w.T (REAL g_acc)

    diag_kernel<<<256, 256>>>(out, (n_in == 11) ? 1 : 13);

    cudaError_t le = cudaGetLastError();
    if (le != cudaSuccess) {
        cudaMemsetAsync((void*)d_out, 0x7F, OUT_SZ * sizeof(float));   // ~3.39e38: launch error
    }
}

// round 16
// speedup vs baseline: 1.2220x; 1.2220x over previous
#include <cuda_runtime.h>
#include <cuda_bf16.h>
#include <cstdint>
#include <cstddef>

#define N_NODES 50000
#define E_EDGES 800000
#define DIM 256
#define H_HEADS 8
#define LAMBDA_INIT 0.63212055882855767840f

// ---------------- scratch (device globals; no allocation allowed) ----------------
__device__ __align__(16) float g_V[(size_t)N_NODES * DIM];     // x @ v_w.T
__device__ __align__(16) float g_acc[(size_t)N_NODES * DIM];   // segment_sum output
__device__ __align__(16) float g_exp[(size_t)E_EDGES * 16];    // exp(edge scores)
__device__ __align__(16) float g_sums[(size_t)N_NODES * 16];   // per-target softmax sums
__device__ int g_src[E_EDGES];
__device__ int g_tgt[E_EDGES];
__device__ int g_is64;
__device__ float g_beta;
__device__ __align__(16) float g_vtest[4];
__device__ int g_vec_ok;

__device__ __forceinline__ void red_add_f32x4_raw(float4* addr, float a, float b, float c, float d) {
    asm volatile("red.global.add.v4.f32 [%0], {%1,%2,%3,%4};"
                 :: "l"(addr), "f"(a), "f"(b), "f"(c), "f"(d) : "memory");
}

__device__ __forceinline__ void red_add4(int vec_ok, float* addr, float a, float b, float c, float d) {
    if (vec_ok) {
        red_add_f32x4_raw((float4*)addr, a, b, c, d);
    } else {
        atomicAdd(addr + 0, a);
        atomicAdd(addr + 1, b);
        atomicAdd(addr + 2, c);
        atomicAdd(addr + 3, d);
    }
}

// ---------------- red.v4 self-test ----------------
__global__ void vtest_init_kernel() { if (threadIdx.x < 4) g_vtest[threadIdx.x] = 0.f; }
__global__ void vtest_run_kernel()  { if (threadIdx.x == 0) red_add_f32x4_raw((float4*)g_vtest, 1.f, 2.f, 3.f, 4.f); }
__global__ void vtest_check_kernel() {
    if (threadIdx.x == 0)
        g_vec_ok = (g_vtest[0] == 1.f && g_vtest[1] == 2.f &&
                    g_vtest[2] == 3.f && g_vtest[3] == 4.f) ? 1 : 0;
}

// ---------------- edge_index dtype detection + canonicalization ----------------
__global__ void detect_kernel(const void* __restrict__ ei) {
    const long long* p = (const long long*)ei;
    int bad = 0;
    for (int i = threadIdx.x; i < 2048; i += 256) {
        long long v = p[i];
        if (v < 0 || v >= N_NODES) bad = 1;
    }
    bad = __syncthreads_or(bad);
    if (threadIdx.x == 0) g_is64 = !bad;
}

__global__ void convert_kernel(const void* __restrict__ ei) {
    int e = blockIdx.x * 256 + threadIdx.x;
    if (e >= E_EDGES) return;
    long long s, t;
    if (g_is64) {
        const long long* p = (const long long*)ei;
        s = p[e];
        t = p[(size_t)E_EDGES + e];
    } else {
        const int* p = (const int*)ei;
        s = p[e];
        t = p[E_EDGES + e];
    }
    if (s < 0) s = 0; if (s >= N_NODES) s = N_NODES - 1;
    if (t < 0) t = 0; if (t >= N_NODES) t = N_NODES - 1;
    g_src[e] = (int)s;
    g_tgt[e] = (int)t;
}

// ---------------- beta ----------------
__global__ void beta_kernel(const float* __restrict__ lq, const float* __restrict__ lk,
                            float* beta_slot) {
    __shared__ float red[4];
    int t = threadIdx.x;
    float v = (t < 100) ? lq[t] * lk[t] : 0.f;
    #pragma unroll
    for (int o = 16; o; o >>= 1) v += __shfl_down_sync(0xffffffffu, v, o);
    if ((t & 31) == 0) red[t >> 5] = v;
    __syncthreads();
    if (t == 0) {
        float s = red[0] + red[1] + red[2] + red[3];
        float lam = expf(s);
        float beta = 1.f / (1.f + expf(-lam * LAMBDA_INIT));
        g_beta = beta;
        if (beta_slot) *beta_slot = beta;
    }
}

// ---------------- zero ----------------
__global__ void zero_kernel() {
    const float4 z = make_float4(0.f, 0.f, 0.f, 0.f);
    size_t stride = (size_t)gridDim.x * blockDim.x;
    size_t i = (size_t)blockIdx.x * blockDim.x + threadIdx.x;
    float4* a = (float4*)g_acc;
    float4* s = (float4*)g_sums;
    for (size_t k = i; k < (size_t)N_NODES * DIM / 4; k += stride) a[k] = z;
    for (size_t k = i; k < (size_t)N_NODES * 16 / 4;  k += stride) s[k] = z;
}

// ---------------- tensor-core bf16x3 GEMM NT: C[i,j] = dot(A[i,:], B[j,:]) ----------------
// fp32 operands split x = hi(bf16) + lo(bf16); C = hi*hi + hi*lo + lo*hi in fp32 accum.
// Block tile 128x64, K-chunk 32, 8 warps each computing 64x16 via m16n8k16 HMMA.
#define AS_STRIDE 40   // 32 bf16 + 8 pad; row stride 80B = 20 banks -> conflict-free ldmatrix

__device__ __forceinline__ uint32_t smem_u32(const void* p) {
    return (uint32_t)__cvta_generic_to_shared(p);
}
__device__ __forceinline__ void ldmx4(uint32_t& r0, uint32_t& r1, uint32_t& r2, uint32_t& r3,
                                      uint32_t addr) {
    asm volatile("ldmatrix.sync.aligned.m8n8.x4.shared.b16 {%0,%1,%2,%3}, [%4];"
                 : "=r"(r0), "=r"(r1), "=r"(r2), "=r"(r3) : "r"(addr));
}
__device__ __forceinline__ void mma16816(float* c, const uint32_t* a, uint32_t b0, uint32_t b1) {
    asm volatile("mma.sync.aligned.m16n8k16.row.col.f32.bf16.bf16.f32 "
                 "{%0,%1,%2,%3},{%4,%5,%6,%7},{%8,%9},{%0,%1,%2,%3};"
                 : "+f"(c[0]), "+f"(c[1]), "+f"(c[2]), "+f"(c[3])
                 : "r"(a[0]), "r"(a[1]), "r"(a[2]), "r"(a[3]), "r"(b0), "r"(b1));
}

__global__ __launch_bounds__(256) void gemm_bf16x3(const float* __restrict__ A,
                                                   const float* __restrict__ B,
                                                   float* __restrict__ C, int M) {
    __shared__ __align__(16) __nv_bfloat16 As_hi[128][AS_STRIDE];
    __shared__ __align__(16) __nv_bfloat16 As_lo[128][AS_STRIDE];
    __shared__ __align__(16) __nv_bfloat16 Bs_hi[64][AS_STRIDE];
    __shared__ __align__(16) __nv_bfloat16 Bs_lo[64][AS_STRIDE];

    const int tid  = threadIdx.x;
    const int lane = tid & 31;
    const int wid  = tid >> 5;
    const int wm   = wid >> 2;      // 0..1 -> 64-row slab
    const int wn   = wid & 3;       // 0..3 -> 16-col slab
    const int bm   = blockIdx.x * 128;
    const int bn   = blockIdx.y * 64;

    float c[4][2][4];
    #pragma unroll
    for (int mt = 0; mt < 4; mt++)
        #pragma unroll
        for (int nt = 0; nt < 2; nt++)
            #pragma unroll
            for (int i = 0; i < 4; i++) c[mt][nt][i] = 0.f;

    for (int kc = 0; kc < 256; kc += 32) {
        // stage A chunk (128 x 32 fp32): 1024 float4, 4 per thread
        #pragma unroll
        for (int i = 0; i < 4; i++) {
            int idx = tid + i * 256;
            int r = idx >> 3, cg = idx & 7;
            int gr = bm + r;
            float4 v = make_float4(0.f, 0.f, 0.f, 0.f);
            if (gr < M) v = *(const float4*)&A[(size_t)gr * 256 + kc + cg * 4];
            __nv_bfloat162 h01 = __floats2bfloat162_rn(v.x, v.y);
            __nv_bfloat162 h23 = __floats2bfloat162_rn(v.z, v.w);
            __nv_bfloat162 l01 = __floats2bfloat162_rn(v.x - __low2float(h01), v.y - __high2float(h01));
            __nv_bfloat162 l23 = __floats2bfloat162_rn(v.z - __low2float(h23), v.w - __high2float(h23));
            *(__nv_bfloat162*)&As_hi[r][cg * 4 + 0] = h01;
            *(__nv_bfloat162*)&As_hi[r][cg * 4 + 2] = h23;
            *(__nv_bfloat162*)&As_lo[r][cg * 4 + 0] = l01;
            *(__nv_bfloat162*)&As_lo[r][cg * 4 + 2] = l23;
        }
        // stage B chunk (64 x 32): 512 float4, 2 per thread
        #pragma unroll
        for (int i = 0; i < 2; i++) {
            int idx = tid + i * 256;
            int r = idx >> 3, cg = idx & 7;
            float4 v = *(const float4*)&B[(size_t)(bn + r) * 256 + kc + cg * 4];
            __nv_bfloat162 h01 = __floats2bfloat162_rn(v.x, v.y);
            __nv_bfloat162 h23 = __floats2bfloat162_rn(v.z, v.w);
            __nv_bfloat162 l01 = __floats2bfloat162_rn(v.x - __low2float(h01), v.y - __high2float(h01));
            __nv_bfloat162 l23 = __floats2bfloat162_rn(v.z - __low2float(h23), v.w - __high2float(h23));
            *(__nv_bfloat162*)&Bs_hi[r][cg * 4 + 0] = h01;
            *(__nv_bfloat162*)&Bs_hi[r][cg * 4 + 2] = h23;
            *(__nv_bfloat162*)&Bs_lo[r][cg * 4 + 0] = l01;
            *(__nv_bfloat162*)&Bs_lo[r][cg * 4 + 2] = l23;
        }
        __syncthreads();

        #pragma unroll
        for (int k16 = 0; k16 < 2; k16++) {
            // A fragments: row = lane%16, k-half by lane/16 (standard x4 recipe)
            uint32_t ah[4][4], al[4][4];
            int arow_in = lane & 15;
            int acol = k16 * 16 + ((lane >> 4) << 3);
            #pragma unroll
            for (int mt = 0; mt < 4; mt++) {
                int row = wm * 64 + mt * 16 + arow_in;
                ldmx4(ah[mt][0], ah[mt][1], ah[mt][2], ah[mt][3], smem_u32(&As_hi[row][acol]));
                ldmx4(al[mt][0], al[mt][1], al[mt][2], al[mt][3], smem_u32(&As_lo[row][acol]));
            }
            // B fragments: x4 covers both n8 tiles (r0,r1 = tile0 k-halves; r2,r3 = tile1)
            uint32_t bh[4], bl[4];
            int nrow = wn * 16 + ((lane >> 4) << 3) + (lane & 7);
            int ncol = k16 * 16 + ((lane >> 3) & 1) * 8;
            ldmx4(bh[0], bh[1], bh[2], bh[3], smem_u32(&Bs_hi[nrow][ncol]));
            ldmx4(bl[0], bl[1], bl[2], bl[3], smem_u32(&Bs_lo[nrow][ncol]));

            #pragma unroll
            for (int mt = 0; mt < 4; mt++)
                #pragma unroll
                for (int nt = 0; nt < 2; nt++) {
                    mma16816(c[mt][nt], ah[mt], bh[nt * 2], bh[nt * 2 + 1]);  // hi*hi
                    mma16816(c[mt][nt], ah[mt], bl[nt * 2], bl[nt * 2 + 1]);  // hi*lo
                    mma16816(c[mt][nt], al[mt], bh[nt * 2], bh[nt * 2 + 1]);  // lo*hi
                }
        }
        __syncthreads();
    }

    // epilogue: c0,c1 -> (row, col/col+1); c2,c3 -> row+8
    #pragma unroll
    for (int mt = 0; mt < 4; mt++) {
        int row0 = bm + wm * 64 + mt * 16 + (lane >> 2);
        int row1 = row0 + 8;
        #pragma unroll
        for (int nt = 0; nt < 2; nt++) {
            int col = bn + wn * 16 + nt * 8 + (lane & 3) * 2;
            if (row0 < M) *(float2*)&C[(size_t)row0 * 256 + col] = make_float2(c[mt][nt][0], c[mt][nt][1]);
            if (row1 < M) *(float2*)&C[(size_t)row1 * 256 + col] = make_float2(c[mt][nt][2], c[mt][nt][3]);
        }
    }
}

// ---------------- edge MLP ----------------
__global__ __launch_bounds__(256) void mlp_kernel(const float* __restrict__ edge_attr,
                                                  const float* __restrict__ w1,
                                                  const float* __restrict__ b1,
                                                  const float* __restrict__ w2,
                                                  const float* __restrict__ b2) {
    __shared__ __align__(16) float s_w1[256 * 8];
    __shared__ float s_b1[256];
    __shared__ __align__(16) float s_w2[16 * 256];
    __shared__ float s_b2[16];
    const int tid = threadIdx.x;
    for (int i = tid; i < 2048; i += 256) {
        int d = i >> 3, j = i & 7;
        s_w1[i] = (j < 6) ? w1[d * 6 + j] : 0.f;
    }
    s_b1[tid] = b1[tid];
    for (int i = tid; i < 4096; i += 256) s_w2[i] = w2[i];
    if (tid < 16) s_b2[tid] = b2[tid];
    __syncthreads();

    const int vec_ok = g_vec_ok;
    const int e = blockIdx.x * 256 + tid;
    float ea0 = edge_attr[(size_t)e * 6 + 0];
    float ea1 = edge_attr[(size_t)e * 6 + 1];
    float ea2 = edge_attr[(size_t)e * 6 + 2];
    float ea3 = edge_attr[(size_t)e * 6 + 3];
    float ea4 = edge_attr[(size_t)e * 6 + 4];
    float ea5 = edge_attr[(size_t)e * 6 + 5];

    float sc[16];
    #pragma unroll
    for (int j = 0; j < 16; j++) sc[j] = s_b2[j];

    for (int c = 0; c < 256; c += 16) {
        float hv[16];
        #pragma unroll
        for (int i = 0; i < 16; i++) {
            int d = c + i;
            float4 wA = *(const float4*)&s_w1[d * 8];
            float4 wB = *(const float4*)&s_w1[d * 8 + 4];
            float z = s_b1[d];
            z = fmaf(wA.x, ea0, z);
            z = fmaf(wA.y, ea1, z);
            z = fmaf(wA.z, ea2, z);
            z = fmaf(wA.w, ea3, z);
            z = fmaf(wB.x, ea4, z);
            z = fmaf(wB.y, ea5, z);
            hv[i] = 0.5f * z * (1.0f + erff(z * 0.70710678118654752f));
        }
        #pragma unroll
        for (int j = 0; j < 16; j++) {
            const float4* wr = (const float4*)&s_w2[j * 256 + c];
            float s = sc[j];
            #pragma unroll
            for (int i2 = 0; i2 < 4; i2++) {
                float4 w = wr[i2];
                s = fmaf(w.x, hv[4 * i2 + 0], s);
                s = fmaf(w.y, hv[4 * i2 + 1], s);
                s = fmaf(w.z, hv[4 * i2 + 2], s);
                s = fmaf(w.w, hv[4 * i2 + 3], s);
            }
            sc[j] = s;
        }
    }
    int tgt = g_tgt[e];
    float ex[16];
    #pragma unroll
    for (int j = 0; j < 16; j++) ex[j] = expf(sc[j]);
    float4* eo = (float4*)&g_exp[(size_t)e * 16];
    #pragma unroll
    for (int q = 0; q < 4; q++) {
        eo[q] = make_float4(ex[4 * q], ex[4 * q + 1], ex[4 * q + 2], ex[4 * q + 3]);
        red_add4(vec_ok, &g_sums[(size_t)tgt * 16 + 4 * q],
                 ex[4 * q], ex[4 * q + 1], ex[4 * q + 2], ex[4 * q + 3]);
    }
}

// ---------------- scatter ----------------
__global__ __launch_bounds__(256) void scatter_kernel(float* __restrict__ d_attn) {
    int gw = (int)(((size_t)blockIdx.x * 256 + threadIdx.x) >> 5);
    int lane = threadIdx.x & 31;
    if (gw >= E_EDGES) return;
    const int vec_ok = g_vec_ok;
    int src = g_src[gw];
    int tgt = g_tgt[gw];
    float beta = g_beta;
    float attn = 0.f;
    if (lane < 8) {
        float2 e12 = ((const float2*)g_exp)[(size_t)gw * 8 + lane];
        float2 s12 = ((const float2*)g_sums)[(size_t)tgt * 8 + lane];
        attn = e12.x / s12.x - beta * (e12.y / s12.y);
        if (d_attn) d_attn[(size_t)gw * 8 + lane] = attn;
    }
    const float4* vsrc = (const float4*)(g_V + (size_t)src * 256);
    float* adst = g_acc + (size_t)tgt * 256;
    #pragma unroll
    for (int h = 0; h < 2; h++) {
        int q = lane + h * 32;
        float w = __shfl_sync(0xffffffffu, attn, q >> 3);
        float4 v = vsrc[q];
        red_add4(vec_ok, adst + 4 * q, w * v.x, w * v.y, w * v.z, w * v.w);
    }
}

// ---------------- diagnostic tripwire ----------------
__global__ void diag_kernel(float* __restrict__ out, int extra_mult) {
    int ok_V = 0, ok_e = 0, ok_s = 0, ok_a = 0, ok_o = 0;
    for (int i = threadIdx.x; i < 4096; i += 256) {
        if (fabsf(g_V[i])   > 1e-12f) ok_V = 1;
        if (g_exp[i]        > 1e-20f) ok_e = 1;
        if (g_sums[i]       > 1e-20f) ok_s = 1;
        if (fabsf(g_acc[i]) > 1e-12f) ok_a = 1;
        if (fabsf(out[i])   > 1e-9f)  ok_o = 1;
    }
    ok_V = __syncthreads_or(ok_V);
    ok_e = __syncthreads_or(ok_e);
    ok_s = __syncthreads_or(ok_s);
    ok_a = __syncthreads_or(ok_a);
    ok_o = __syncthreads_or(ok_o);
    float code = 0.f;
    if      (!ok_V) code = 1e2f;
    else if (!ok_e) code = 1e4f;
    else if (!ok_s) code = 1e6f;
    else if (!ok_a) code = 1e8f;
    else if (!ok_o) code = 1e10f;
    if (code != 0.f) {
        code *= (g_is64 ? 1.f : 3.f);
        code *= (g_vec_ok ? 1.f : 7.f);
        code *= (float)extra_mult;
        size_t stride = (size_t)gridDim.x * blockDim.x;
        for (size_t i = (size_t)blockIdx.x * blockDim.x + threadIdx.x;
             i < (size_t)N_NODES * DIM; i += stride)
            out[i] = code;
    }
}

// ---------------- launch ----------------
extern "C" void kernel_launch(void* const* d_in, const int* in_sizes, int n_in,
                              void* d_out, int out_size) {
    int i_x = -1, i_ea = -1, i_ei = -1, i_w1 = -1, i_b1 = -1, i_w2 = -1, i_b2 = -1;
    int sq65536[2] = {-1, -1};
    int sq100[2]   = {-1, -1};
    for (int i = 0; i < n_in; i++) {
        int s = in_sizes[i];
        switch (s) {
            case 12800000: i_x = i; break;
            case 4800000:  i_ea = i; break;
            case 1600000: case 3200000: i_ei = i; break;
            case 1536:     i_w1 = i; break;
            case 256:      i_b1 = i; break;
            case 4096:     i_w2 = i; break;
            case 16:       i_b2 = i; break;
            case 65536:    if (sq65536[0] < 0) sq65536[0] = i; else sq65536[1] = i; break;
            case 100:      if (sq100[0] < 0) sq100[0] = i; else sq100[1] = i; break;
            default: break;
        }
    }
    const size_t OUT_SZ  = (size_t)N_NODES * DIM;
    const size_t ATTN_SZ = (size_t)E_EDGES * H_HEADS;

    bool found = (i_x >= 0) && (i_ea >= 0) && (i_ei >= 0) && (i_w1 >= 0) && (i_b1 >= 0) &&
                 (i_w2 >= 0) && (i_b2 >= 0) && (sq65536[1] >= 0) && (sq100[1] >= 0);
    if (!found) {
        cudaMemsetAsync((void*)d_out, 0x7E, OUT_SZ * sizeof(float));
        return;
    }

    // real device addresses of __device__ globals (host shadows are wrong under ATS)
    float *pV = nullptr, *pAcc = nullptr;
    cudaGetSymbolAddress((void**)&pV, g_V);
    cudaGetSymbolAddress((void**)&pAcc, g_acc);
    if (!pV || !pAcc) {
        cudaMemsetAsync((void*)d_out, 0x7D, OUT_SZ * sizeof(float));
        return;
    }

    int i_vw, i_ow;
    if (i_x == 0) { i_vw = sq65536[0]; i_ow = sq65536[1]; }
    else          { i_ow = sq65536[0]; i_vw = sq65536[1]; }

    const float* x         = (const float*)d_in[i_x];
    const float* edge_attr = (const float*)d_in[i_ea];
    const float* v_w       = (const float*)d_in[i_vw];
    const float* out_w     = (const float*)d_in[i_ow];
    const float* e_w1      = (const float*)d_in[i_w1];
    const float* e_b1      = (const float*)d_in[i_b1];
    const float* e_w2      = (const float*)d_in[i_w2];
    const float* e_b2      = (const float*)d_in[i_b2];
    const float* lq        = (const float*)d_in[sq100[0]];
    const float* lk        = (const float*)d_in[sq100[1]];
    const void*  ei        = (const void*)d_in[i_ei];

    float* out = (float*)d_out;
    float* d_attn = nullptr;
    float* d_beta = nullptr;
    if ((size_t)out_size >= OUT_SZ + ATTN_SZ)     d_attn = out + OUT_SZ;
    if ((size_t)out_size >= OUT_SZ + ATTN_SZ + 1) d_beta = out + OUT_SZ + ATTN_SZ;

    cudaGetLastError();

    vtest_init_kernel<<<1, 32>>>();
    vtest_run_kernel<<<1, 32>>>();
    vtest_check_kernel<<<1, 32>>>();

    detect_kernel<<<1, 256>>>(ei);
    convert_kernel<<<(E_EDGES + 255) / 256, 256>>>(ei);

    beta_kernel<<<1, 128>>>(lq, lk, d_beta);
    zero_kernel<<<1024, 256>>>();

    dim3 ggrid((N_NODES + 127) / 128, DIM / 64);
    gemm_bf16x3<<<ggrid, 256>>>(x, v_w, pV, N_NODES);              // V = x @ v_w.T (tensor cores)

    mlp_kernel<<<E_EDGES / 256, 256>>>(edge_attr, e_w1, e_b1, e_w2, e_b2);

    scatter_kernel<<<E_EDGES / 8, 256>>>(d_attn);                  // 1 warp per edge

    gemm_bf16x3<<<ggrid, 256>>>(pAcc, out_w, out, N_NODES);        // out = acc @ out_w.T

    diag_kernel<<<256, 256>>>(out, (n_in == 11) ? 1 : 13);

    cudaError_t le = cudaGetLastError();
    if (le != cudaSuccess) {
        cudaMemsetAsync((void*)d_out, 0x7F, OUT_SZ * sizeof(float));
    }
}